// round 2
// baseline (speedup 1.0000x reference)
#include <cuda_runtime.h>

#define N_OBSV 256
#define NYV 50
#define NXV 30
#define ITERS 400
#define LRV 0.05f
#define EP_PITCH 51

// dynamic smem layout (float offsets)
#define OFF_EP   0            // [256][51] = 13056
#define OFF_YH   13056        // 64
#define OFF_ZC   13120        // z[0..49], c at [50]
#define OFF_R    13184        // 256 (16B aligned: 13184*4 % 16 == 0)
#define OFF_Q    13440        // 256
#define OFF_PART 13696        // 8*52 = 416
#define OFF_QW   14112        // 8
#define OFF_V    14120        // 64
#define OFF_U    14184        // 64
#define OFF_CS   14248        // 64
#define SMEM_FLOATS 14312
#define SMEM_BYTES (SMEM_FLOATS * 4)

__global__ void __launch_bounds__(256, 2)
dro_kernel(const float* __restrict__ X, const float* __restrict__ Y,
           const float* __restrict__ W, const float* __restrict__ b,
           const float* __restrict__ pdelta, const float* __restrict__ pgamma,
           float* __restrict__ out)
{
    extern __shared__ float sm[];
    float* EP   = sm + OFF_EP;
    float* YH   = sm + OFF_YH;
    float* ZC   = sm + OFF_ZC;
    float* RB   = sm + OFF_R;
    float* QB   = sm + OFF_Q;
    float* PART = sm + OFF_PART;
    float* QW   = sm + OFF_QW;
    float* VB   = sm + OFF_V;
    float* UB   = sm + OFF_U;
    float* CS   = sm + OFF_CS;

    const int t    = blockIdx.x;
    const int tid  = threadIdx.x;
    const int lane = tid & 31;
    const int wid  = tid >> 5;

    const float delta = *pdelta;
    const float gamma = *pgamma;
    const float a_val = fminf(delta * 0.5f, 255.0f / 256.0f);

    // ---- prologue: ep row `tid` = Y[tid] - (X[tid] @ W^T + b) ----
    {
        float xr[NXV];
        #pragma unroll
        for (int j = 0; j < NXV; j++) xr[j] = X[tid * NXV + j];
        for (int k = 0; k < NYV; k++) {
            float s = b[k];
            #pragma unroll
            for (int j = 0; j < NXV; j++) s = fmaf(xr[j], W[k * NXV + j], s);
            EP[tid * EP_PITCH + k] = Y[tid * NYV + k] - s;
        }
    }
    if (tid < NYV)  ZC[tid] = 1.0f / 50.0f;   // z0
    if (tid == NYV) ZC[NYV] = 0.0f;           // c0
    __syncthreads();

    // y_hat for this CTA's scenario; also emit Y_hat output row t
    if (tid < NYV) {
        float yh = Y[t * NYV + tid] - EP[t * EP_PITCH + tid];
        YH[tid] = yh;
        out[N_OBSV * NYV + t * NYV + tid] = yh;
    }

    // ---- 400 PGD iterations ----
    for (int it = 0; it < ITERS; it++) {
        __syncthreads();   // z, c (and YH on it==0) visible

        // step 1: e_i = ep_i @ z - c ; r_i = e_i^2
        float e = -ZC[NYV];
        {
            const float* row = EP + tid * EP_PITCH;
            #pragma unroll
            for (int k = 0; k < NYV; k++) e = fmaf(row[k], ZC[k], e);
        }
        const float r = e * e;
        RB[tid] = r;
        __syncthreads();

        // step 2: rank by counting (stable ascending); p_i ; q_i = 2 p_i e_i
        int cnt = 0;
        {
            const float4* r4 = (const float4*)RB;
            #pragma unroll 8
            for (int j = 0; j < N_OBSV / 4; j++) {
                float4 v = r4[j];
                cnt += (v.x < r) + (v.y < r) + (v.z < r) + (v.w < r);
            }
        }
        float wgt = fminf(fmaxf(a_val - (float)cnt * (1.0f / 256.0f), 0.0f),
                          1.0f / 256.0f);
        float p = 1.0f / 256.0f - wgt;
        if (cnt == N_OBSV - 1) p += a_val;     // max element (grad of a*max(r))
        const float q = 2.0f * p * e;
        QB[tid] = q;
        float qs = q;
        #pragma unroll
        for (int off = 16; off; off >>= 1)
            qs += __shfl_xor_sync(0xffffffffu, qs, off);
        if (lane == 0) QW[wid] = qs;
        __syncthreads();

        // step 3: partial gz: warp `wid` handles rows [32w, 32w+32)
        {
            float acc0 = 0.0f, acc1 = 0.0f;
            const int rb = wid * 32;
            #pragma unroll 8
            for (int rr = 0; rr < 32; rr++) {
                const int i = rb + rr;
                const float qi = QB[i];                // broadcast
                const float* row = EP + i * EP_PITCH;
                acc0 = fmaf(row[lane], qi, acc0);
                if (lane < NYV - 32) acc1 = fmaf(row[lane + 32], qi, acc1);
            }
            PART[wid * 52 + lane] = acc0;
            if (lane < NYV - 32) PART[wid * 52 + lane + 32] = acc1;
        }
        __syncthreads();

        // step 4: gz, gc; v = z - LR*gz ; c -= LR*gc
        if (tid < NYV) {
            float g = 0.0f;
            #pragma unroll
            for (int w = 0; w < 8; w++) g += PART[w * 52 + tid];
            g -= gamma * YH[tid];
            VB[tid] = ZC[tid] - LRV * g;
        } else if (tid == 64) {
            float s = 0.0f;
            #pragma unroll
            for (int w = 0; w < 8; w++) s += QW[w];
            ZC[NYV] = ZC[NYV] + LRV * s;   // gc = -sum(q)
        }
        __syncthreads();

        // step 5: project v onto the simplex (stable desc order by counting)
        float vk = 0.0f;
        if (tid < NYV) {
            vk = VB[tid];
            int c2 = 0;
            #pragma unroll
            for (int j = 0; j < NYV; j++) {
                float vj = VB[j];
                c2 += (int)((vj < vk) | ((vj == vk) & (j < tid)));
            }
            UB[(NYV - 1) - c2] = vk;   // descending order
        }
        __syncthreads();

        float u = 0.0f, cs = 0.0f;
        if (tid < 64) {
            u  = (tid < NYV) ? UB[tid] : 0.0f;
            cs = u;
            #pragma unroll
            for (int off = 1; off < 32; off <<= 1) {
                float nb = __shfl_up_sync(0xffffffffu, cs, off);
                if (lane >= off) cs += nb;
            }
            if (tid == 31) CS[63] = cs;    // warp0 total
        }
        __syncthreads();
        int pred = 0;
        if (tid < NYV) {
            if (tid >= 32) cs += CS[63];
            CS[tid] = cs;                  // inclusive cumsum of u
            pred = (u - (cs - 1.0f) / (float)(tid + 1)) > 0.0f;
        }
        const int rho = __syncthreads_count(pred);
        const float tau = (CS[rho - 1] - 1.0f) / (float)rho;
        if (tid < NYV) ZC[tid] = fmaxf(vk - tau, 0.0f);
    }

    __syncthreads();
    if (tid < NYV) out[t * NYV + tid] = ZC[tid];
}

extern "C" void kernel_launch(void* const* d_in, const int* in_sizes, int n_in,
                              void* d_out, int out_size)
{
    const float* X     = (const float*)d_in[0];
    const float* Y     = (const float*)d_in[1];
    const float* W     = (const float*)d_in[2];
    const float* b     = (const float*)d_in[3];
    const float* delta = (const float*)d_in[4];
    const float* gamma = (const float*)d_in[5];
    float* out = (float*)d_out;

    cudaFuncSetAttribute(dro_kernel,
                         cudaFuncAttributeMaxDynamicSharedMemorySize,
                         SMEM_BYTES);
    dro_kernel<<<N_OBSV, 256, SMEM_BYTES>>>(X, Y, W, b, delta, gamma, out);
}

// round 6
// speedup vs baseline: 1.0474x; 1.0474x over previous
#include <cuda_runtime.h>

#define N_OBSV 256
#define NYV 50
#define NXV 30
#define ITERS 400
#define LRV 0.05f
#define EPP 52                // ep pitch (float4-friendly, conflict-free)
#define CAP 128               // candidate capacity
#define INV256 0.00390625f

// dynamic smem layout (float offsets)
#define OFF_EP    0           // [256][52] = 13312 (rows 16B aligned)
#define OFF_ZC    13312       // z[0..49], pads 50,51 = 0 (16B aligned)
#define OFF_YH    13364       // 52
#define OFF_VB    13416       // 52
#define OFF_UB    13468       // 52
#define OFF_CS    13520       // 64
#define OFF_QB    13584       // 256
#define OFF_RB    13840       // 256
#define OFF_PART  14096       // 8*52 = 416
#define OFF_WM    14512       // 8 (warp maxes)
#define OFF_QW    14520       // 8 (warp q-sums)
#define OFF_CC    14528       // 1 (scalar c)
#define OFF_NC    14529       // 1 (int candidate counter)
#define OFF_CAND  14532       // 128
#define SMEM_FLOATS 14660
#define SMEM_BYTES (SMEM_FLOATS * 4)

__global__ void __launch_bounds__(256, 2)
dro_kernel(const float* __restrict__ X, const float* __restrict__ Y,
           const float* __restrict__ W, const float* __restrict__ b,
           const float* __restrict__ pdelta, const float* __restrict__ pgamma,
           float* __restrict__ out)
{
    extern __shared__ float sm[];
    float* EP    = sm + OFF_EP;
    float* ZC    = sm + OFF_ZC;
    float* YH    = sm + OFF_YH;
    float* VB    = sm + OFF_VB;
    float* UB    = sm + OFF_UB;
    float* CS    = sm + OFF_CS;
    float* QB    = sm + OFF_QB;
    float* RB    = sm + OFF_RB;
    float* PART  = sm + OFF_PART;
    float* WM    = sm + OFF_WM;
    float* QW    = sm + OFF_QW;
    float* CC    = sm + OFF_CC;
    int*   NC    = (int*)(sm + OFF_NC);
    float* CANDV = sm + OFF_CAND;

    const int t    = blockIdx.x;
    const int tid  = threadIdx.x;
    const int lane = tid & 31;
    const int wid  = tid >> 5;

    const float delta = *pdelta;
    const float gamma = *pgamma;
    const float a_val = fminf(delta * 0.5f, 255.0f / 256.0f);
    int Kneed = (int)(a_val * 256.0f) + 1;
    if (Kneed > 127) Kneed = 127;

    // ---- prologue: ep row `tid` = Y[tid] - (X[tid] @ W^T + b) ----
    {
        float xr[NXV];
        #pragma unroll
        for (int j = 0; j < NXV; j++) xr[j] = X[tid * NXV + j];
        for (int k = 0; k < NYV; k++) {
            float s = b[k];
            #pragma unroll
            for (int j = 0; j < NXV; j++) s = fmaf(xr[j], W[k * NXV + j], s);
            EP[tid * EPP + k] = Y[tid * NYV + k] - s;
        }
        EP[tid * EPP + 50] = 0.0f;
        EP[tid * EPP + 51] = 0.0f;
    }
    if (tid < NYV)  ZC[tid] = 1.0f / 50.0f;            // z0
    if (tid == 50 || tid == 51) ZC[tid] = 0.0f;        // pads
    if (tid == 0) *CC = 0.0f;                          // c0
    __syncthreads();

    // y_hat for this CTA's scenario; emit Y_hat output row t
    if (tid < NYV) {
        float yh = Y[t * NYV + tid] - EP[t * EPP + tid];
        YH[tid] = yh;
        out[N_OBSV * NYV + t * NYV + tid] = yh;
    }

    // ---- 400 PGD iterations ----
    for (int it = 0; it < ITERS; it++) {
        __syncthreads();   // z, c (and YH on it==0) visible

        // ===== step 1: e_i = ep_i @ z - c (vectorized) =====
        float e = -(*CC);
        {
            const float4* row4 = (const float4*)(EP + tid * EPP);
            const float4* z4   = (const float4*)ZC;
            #pragma unroll
            for (int j = 0; j < 13; j++) {
                float4 rv = row4[j], zv = z4[j];
                e = fmaf(rv.x, zv.x, e);
                e = fmaf(rv.y, zv.y, e);
                e = fmaf(rv.z, zv.z, e);
                e = fmaf(rv.w, zv.w, e);
            }
        }
        const float r = e * e;
        RB[tid] = r;

        // warp max partials (also needed for argmax term)
        float wm = r;
        #pragma unroll
        for (int off = 16; off; off >>= 1)
            wm = fmaxf(wm, __shfl_xor_sync(0xffffffffu, wm, off));
        if (lane == 0) WM[wid] = wm;
        if (tid == 0) *NC = 0;
        __syncthreads();

        float maxv = WM[0];
        #pragma unroll
        for (int w = 1; w < 8; w++) maxv = fmaxf(maxv, WM[w]);

        // ===== step 2: find threshold T with Kneed <= count(r<T) <= CAP =====
        float lo = 0.0f, hi = maxv, goodT = 3.4e38f;
        int goodC = N_OBSV;
        for (int bs = 0; bs < 8; bs++) {
            float mid = 0.5f * (lo + hi);
            int c = __syncthreads_count(r < mid);
            if (c >= Kneed) {
                goodT = mid; goodC = c; hi = mid;
                if (c <= CAP) break;        // uniform (c is CTA-uniform)
            } else {
                lo = mid;
            }
        }

        const bool fb = (goodC > CAP);       // fallback (shouldn't trigger)
        int slot = -1;
        if (!fb && (r < goodT)) slot = atomicAdd(NC, 1);
        if (slot >= 0) CANDV[slot] = r;
        const int nmax = __syncthreads_count(r == maxv);  // orders CANDV too

        int cnt = 0;
        float wgt = 0.0f;
        if (fb) {
            for (int j = 0; j < N_OBSV; j++) cnt += RB[j] < r;
            wgt = fminf(fmaxf(a_val - (float)cnt * INV256, 0.0f), INV256);
        } else if (r < goodT) {
            for (int j = 0; j < goodC; j++) cnt += CANDV[j] < r;
            wgt = fminf(fmaxf(a_val - (float)cnt * INV256, 0.0f), INV256);
        }
        float p = INV256 - wgt;
        if (r == maxv) p += a_val / (float)nmax;
        const float q = 2.0f * p * e;
        QB[tid] = q;
        float qs = q;
        #pragma unroll
        for (int off = 16; off; off >>= 1)
            qs += __shfl_xor_sync(0xffffffffu, qs, off);
        if (lane == 0) QW[wid] = qs;
        __syncthreads();

        // ===== step 3: partial gz: warp `wid` handles rows [32w, 32w+32) =====
        {
            float acc0 = 0.0f, acc1 = 0.0f;
            const int rb = wid * 32;
            #pragma unroll 8
            for (int rr = 0; rr < 32; rr++) {
                const int i = rb + rr;
                const float qi = QB[i];                // broadcast
                const float* row = EP + i * EPP;
                acc0 = fmaf(row[lane], qi, acc0);
                if (lane < NYV - 32) acc1 = fmaf(row[lane + 32], qi, acc1);
            }
            PART[wid * 52 + lane] = acc0;
            if (lane < NYV - 32) PART[wid * 52 + lane + 32] = acc1;
        }
        __syncthreads();

        // ===== step 4: gz, gc; v = z - LR*gz ; c -= LR*gc =====
        if (tid < NYV) {
            float g = 0.0f;
            #pragma unroll
            for (int w = 0; w < 8; w++) g += PART[w * 52 + tid];
            g -= gamma * YH[tid];
            VB[tid] = ZC[tid] - LRV * g;
        } else if (tid == 64) {
            float s = 0.0f;
            #pragma unroll
            for (int w = 0; w < 8; w++) s += QW[w];
            *CC = *CC + LRV * s;               // gc = -sum(q)
        }
        __syncthreads();

        // ===== step 5: project v onto simplex (stable desc order by count) =====
        float vk = 0.0f;
        if (tid < NYV) {
            vk = VB[tid];
            int c2 = 0;
            #pragma unroll
            for (int j = 0; j < NYV; j++) {
                float vj = VB[j];
                c2 += (int)((vj < vk) | ((vj == vk) & (j < tid)));
            }
            UB[(NYV - 1) - c2] = vk;           // descending order
        }
        __syncthreads();

        float u = 0.0f, cs = 0.0f;
        if (tid < 64) {
            u  = (tid < NYV) ? UB[tid] : 0.0f;
            cs = u;
            #pragma unroll
            for (int off = 1; off < 32; off <<= 1) {
                float nb = __shfl_up_sync(0xffffffffu, cs, off);
                if (lane >= off) cs += nb;
            }
            if (tid == 31) CS[63] = cs;        // warp0 total
        }
        __syncthreads();
        int pred = 0;
        if (tid < NYV) {
            if (tid >= 32) cs += CS[63];
            CS[tid] = cs;                      // inclusive cumsum of u
            pred = (u - (cs - 1.0f) / (float)(tid + 1)) > 0.0f;
        }
        const int rho = __syncthreads_count(pred);
        const float tau = (CS[rho - 1] - 1.0f) / (float)rho;
        if (tid < NYV) ZC[tid] = fmaxf(vk - tau, 0.0f);
    }

    __syncthreads();
    if (tid < NYV) out[t * NYV + tid] = ZC[tid];
}

extern "C" void kernel_launch(void* const* d_in, const int* in_sizes, int n_in,
                              void* d_out, int out_size)
{
    const float* X     = (const float*)d_in[0];
    const float* Y     = (const float*)d_in[1];
    const float* W     = (const float*)d_in[2];
    const float* b     = (const float*)d_in[3];
    const float* delta = (const float*)d_in[4];
    const float* gamma = (const float*)d_in[5];
    float* out = (float*)d_out;

    cudaFuncSetAttribute(dro_kernel,
                         cudaFuncAttributeMaxDynamicSharedMemorySize,
                         SMEM_BYTES);
    dro_kernel<<<N_OBSV, 256, SMEM_BYTES>>>(X, Y, W, b, delta, gamma, out);
}

// round 8
// speedup vs baseline: 1.2785x; 1.2207x over previous
#include <cuda_runtime.h>

#define N_OBSV 256
#define NYV 50
#define NXV 30
#define ITERS 400
#define LRV 0.05f
#define EPP 52                // ep pitch in floats (float4-friendly, conflict-free)
#define CAPC 64               // candidate capacity for pruned ranking
#define INV256 0.00390625f

// dynamic smem layout (float offsets)
#define OFF_EP    0           // [256][52] = 13312 (rows 16B aligned)
#define OFF_ZC    13312       // z[0..49], pads 50,51 = 0 (16B aligned)
#define OFF_YH    13364       // 52
#define OFF_VB    13416       // 52
#define OFF_EB    13468       // 256 residuals e
#define OFF_RB    13724       // 256 residuals squared r
#define OFF_PART  13980       // 8*52 = 416
#define OFF_WM    14396       // 8 warp maxes
#define OFF_ES    14404       // 8 warp e-sums
#define OFF_CANDV 14412       // 64 (+pad)
#define OFF_CORRI 14480       // 272 (int)
#define OFF_CORRD 14752       // 272
#define OFF_NC    15024       // int
#define OFF_NC2   15025       // int
#define OFF_TAU   15026       // float
#define OFF_CC    15027       // float (scalar c)
#define SMEM_FLOATS 15028
#define SMEM_BYTES (SMEM_FLOATS * 4)

__global__ void __launch_bounds__(256, 2)
dro_kernel(const float* __restrict__ X, const float* __restrict__ Y,
           const float* __restrict__ W, const float* __restrict__ b,
           const float* __restrict__ pdelta, const float* __restrict__ pgamma,
           float* __restrict__ out)
{
    extern __shared__ float sm[];
    float* EP    = sm + OFF_EP;
    float* ZC    = sm + OFF_ZC;
    float* YH    = sm + OFF_YH;
    float* VB    = sm + OFF_VB;
    float* EB    = sm + OFF_EB;
    float* RB    = sm + OFF_RB;
    float* PART  = sm + OFF_PART;
    float* WM    = sm + OFF_WM;
    float* ES    = sm + OFF_ES;
    float* CANDV = sm + OFF_CANDV;
    int*   CORRI = (int*)(sm + OFF_CORRI);
    float* CORRD = sm + OFF_CORRD;
    int*   NC    = (int*)(sm + OFF_NC);
    int*   NC2   = (int*)(sm + OFF_NC2);
    float* TAU   = sm + OFF_TAU;
    float* CC    = sm + OFF_CC;

    const int t    = blockIdx.x;
    const int tid  = threadIdx.x;
    const int lane = tid & 31;
    const int wid  = tid >> 5;

    const float delta = *pdelta;
    const float gamma = *pgamma;
    const float a_val = fminf(delta * 0.5f, 255.0f / 256.0f);
    int Kneed = (int)(a_val * 256.0f) + 1;
    if (Kneed > CAPC - 1) Kneed = CAPC - 1;

    // ---- prologue: ep row `tid` = Y[tid] - (X[tid] @ W^T + b) ----
    {
        float xr[NXV];
        #pragma unroll
        for (int j = 0; j < NXV; j++) xr[j] = X[tid * NXV + j];
        for (int k = 0; k < NYV; k++) {
            float s = b[k];
            #pragma unroll
            for (int j = 0; j < NXV; j++) s = fmaf(xr[j], W[k * NXV + j], s);
            EP[tid * EPP + k] = Y[tid * NYV + k] - s;
        }
        EP[tid * EPP + 50] = 0.0f;
        EP[tid * EPP + 51] = 0.0f;
    }
    if (tid < NYV)  ZC[tid] = 1.0f / 50.0f;            // z0
    if (tid == 50 || tid == 51) ZC[tid] = 0.0f;        // pads
    if (tid == 0) *CC = 0.0f;                          // c0
    __syncthreads();

    // y_hat for this CTA's scenario; emit Y_hat output row t
    if (tid < NYV) {
        float yh = Y[t * NYV + tid] - EP[t * EPP + tid];
        YH[tid] = yh;
        out[N_OBSV * NYV + t * NYV + tid] = yh;
    }

    float prevT = -1.0f;   // warm-start threshold (CTA-uniform by construction)

    // ---- 400 PGD iterations ----
    for (int it = 0; it < ITERS; it++) {
        __syncthreads();   // B0: z, c (and YH on it==0) visible

        // ===== step 1: e_i = ep_i @ z - c (4 independent FMA chains) =====
        float e0 = 0.f, e1 = 0.f, e2 = 0.f, e3 = 0.f;
        {
            const float4* row4 = (const float4*)(EP + tid * EPP);
            const float4* z4   = (const float4*)ZC;
            #pragma unroll
            for (int j = 0; j < 12; j += 4) {
                float4 r0 = row4[j],   zv0 = z4[j];
                float4 r1 = row4[j+1], zv1 = z4[j+1];
                float4 r2 = row4[j+2], zv2 = z4[j+2];
                float4 r3 = row4[j+3], zv3 = z4[j+3];
                e0 = fmaf(r0.x, zv0.x, e0); e0 = fmaf(r0.y, zv0.y, e0);
                e0 = fmaf(r0.z, zv0.z, e0); e0 = fmaf(r0.w, zv0.w, e0);
                e1 = fmaf(r1.x, zv1.x, e1); e1 = fmaf(r1.y, zv1.y, e1);
                e1 = fmaf(r1.z, zv1.z, e1); e1 = fmaf(r1.w, zv1.w, e1);
                e2 = fmaf(r2.x, zv2.x, e2); e2 = fmaf(r2.y, zv2.y, e2);
                e2 = fmaf(r2.z, zv2.z, e2); e2 = fmaf(r2.w, zv2.w, e2);
                e3 = fmaf(r3.x, zv3.x, e3); e3 = fmaf(r3.y, zv3.y, e3);
                e3 = fmaf(r3.z, zv3.z, e3); e3 = fmaf(r3.w, zv3.w, e3);
            }
            float4 rv = row4[12], zv = z4[12];
            e0 = fmaf(rv.x, zv.x, e0); e1 = fmaf(rv.y, zv.y, e1);
            e2 = fmaf(rv.z, zv.z, e2); e3 = fmaf(rv.w, zv.w, e3);
        }
        const float e = ((e0 + e1) + (e2 + e3)) - (*CC);
        const float r = e * e;
        EB[tid] = e;
        RB[tid] = r;

        // warp max (argmax term) and warp e-sum (gc base) — independent trees
        float wm = r, es = e;
        #pragma unroll
        for (int off = 16; off; off >>= 1) {
            wm = fmaxf(wm, __shfl_xor_sync(0xffffffffu, wm, off));
            es += __shfl_xor_sync(0xffffffffu, es, off);
        }
        if (lane == 0) { WM[wid] = wm; ES[wid] = es; }
        if (tid == 0) { *NC = 0; *NC2 = 0; }
        __syncthreads();   // B1

        float maxv = WM[0];
        #pragma unroll
        for (int w = 1; w < 8; w++) maxv = fmaxf(maxv, WM[w]);

        // ===== step 2: threshold with warm start =====
        float lo = 0.0f, hi = maxv;
        float T = (prevT > 0.0f) ? prevT : 0.5f * maxv;
        float goodT = 0.0f;
        int   goodC = -1;
        #pragma unroll 1
        for (int bs = 0; bs < 10; bs++) {
            int c = __syncthreads_count(r < T);          // C-count
            if (c >= Kneed && c <= CAPC) { goodT = T; goodC = c; break; }
            if (c < Kneed) lo = T; else hi = T;
            T = 0.5f * (lo + hi);
        }
        if (goodC > 0) prevT = goodT;

        const bool iscand = (goodC > 0) && (r < goodT);
        if (iscand) {
            int slot = atomicAdd(NC, 1);
            CANDV[slot] = r;
        }
        const int nmax = __syncthreads_count(r == maxv); // C2: also orders CANDV

        // sparse correction dq_i = 2(p_i - 1/256) e_i
        float dq = 0.0f;
        if (goodC < 0) {                                  // fallback: full count
            int cnt = 0;
            for (int j = 0; j < N_OBSV; j++) cnt += RB[j] < r;
            float wgt = fminf(fmaxf(a_val - (float)cnt * INV256, 0.0f), INV256);
            dq -= 2.0f * wgt * e;
        } else if (iscand) {
            int cnt = 0;
            for (int j = 0; j < goodC; j++) cnt += CANDV[j] < r;
            float wgt = fminf(fmaxf(a_val - (float)cnt * INV256, 0.0f), INV256);
            dq -= 2.0f * wgt * e;
        }
        if (r == maxv) dq += (2.0f * a_val / (float)nmax) * e;
        if (dq != 0.0f) {
            int m = atomicAdd(NC2, 1);
            CORRI[m] = tid;
            CORRD[m] = dq;
        }

        // ===== step 3 (overlapped): base matvec PART = ep^T e, warp-sliced =====
        {
            float a0 = 0.f, a1 = 0.f, b0v = 0.f, b1v = 0.f;
            const int rb = wid * 32;
            #pragma unroll 4
            for (int rr = 0; rr < 32; rr += 2) {
                const int i0 = rb + rr, i1 = rb + rr + 1;
                const float q0 = EB[i0], q1 = EB[i1];     // broadcast
                a0 = fmaf(EP[i0 * EPP + lane], q0, a0);
                a1 = fmaf(EP[i1 * EPP + lane], q1, a1);
                if (lane < NYV - 32) {
                    b0v = fmaf(EP[i0 * EPP + lane + 32], q0, b0v);
                    b1v = fmaf(EP[i1 * EPP + lane + 32], q1, b1v);
                }
            }
            PART[wid * 52 + lane] = a0 + a1;
            if (lane < NYV - 32) PART[wid * 52 + lane + 32] = b0v + b1v;
        }
        __syncthreads();   // B2: PART + CORR list ready

        // ===== step 4: gz = (2/256) ep^T e + ep^T dq - gamma*yhat =====
        const int M = *NC2;
        if (tid < NYV) {
            float g = 0.0f;
            #pragma unroll
            for (int w = 0; w < 8; w++) g += PART[w * 52 + tid];
            g *= 2.0f * INV256;
            for (int m = 0; m < M; m++)
                g = fmaf(CORRD[m], EP[CORRI[m] * EPP + tid], g);
            g -= gamma * YH[tid];
            VB[tid] = ZC[tid] - LRV * g;
        } else if (tid == 64) {
            float esum = 0.0f;
            #pragma unroll
            for (int w = 0; w < 8; w++) esum += ES[w];
            float ds = 0.0f;
            for (int m = 0; m < M; m++) ds += CORRD[m];
            *CC = *CC + LRV * (2.0f * INV256 * esum + ds);  // c -= LR*gc
        }
        __syncthreads();   // B3

        // ===== step 5: simplex projection, scan-free =====
        float vk = 0.0f, cs = 0.0f;
        int cb = 0, pred = 0;
        if (tid < NYV) {
            vk = VB[tid];
            float s = 0.0f;
            #pragma unroll
            for (int j = 0; j < NYV; j++) {
                float vj = VB[j];
                bool before = (vj > vk) | ((vj == vk) & (j < tid));
                cb += (int)before;
                s  += before ? vj : 0.0f;
            }
            cs = s + vk;                       // inclusive cumsum at desc pos cb
            pred = (vk - (cs - 1.0f) / (float)(cb + 1)) > 0.0f;
        }
        const int rho = __syncthreads_count(pred);   // C3
        if (tid < NYV && cb == rho - 1)
            *TAU = (cs - 1.0f) / (float)rho;
        __syncthreads();   // B4
        if (tid < NYV) ZC[tid] = fmaxf(vk - *TAU, 0.0f);
    }

    __syncthreads();
    if (tid < NYV) out[t * NYV + tid] = ZC[tid];
}

extern "C" void kernel_launch(void* const* d_in, const int* in_sizes, int n_in,
                              void* d_out, int out_size)
{
    const float* X     = (const float*)d_in[0];
    const float* Y     = (const float*)d_in[1];
    const float* W     = (const float*)d_in[2];
    const float* b     = (const float*)d_in[3];
    const float* delta = (const float*)d_in[4];
    const float* gamma = (const float*)d_in[5];
    float* out = (float*)d_out;

    cudaFuncSetAttribute(dro_kernel,
                         cudaFuncAttributeMaxDynamicSharedMemorySize,
                         SMEM_BYTES);
    dro_kernel<<<N_OBSV, 256, SMEM_BYTES>>>(X, Y, W, b, delta, gamma, out);
}